// round 14
// baseline (speedup 1.0000x reference)
#include <cuda_runtime.h>

#define Wd 512
#define Hd 256
#define Bd 4
#define HW (Hd*Wd)
#define NP (Bd*HW)
#define TX 32
#define TY 4
#define VY 2
#define TILEH (TY*VY)      // 8
#define SW (TX+4)          // 36
#define SH (TILEH+4)       // 12
#define NTHR (TX*TY)       // 128

// Scratch (static __device__ arrays; no cudaMalloc allowed)
__device__ float4 g_w4[6*NP];  // weights k=0..23 packed as float4 planes
__device__ float  g_w1[NP];    // weight k=24
__device__ float  g_is[NP];    // 1/sum(w)
__device__ float  g_PA[3*NP];
__device__ float  g_PB[3*NP];

// ---------------------------------------------------------------------------
// k_pre: V=2 pixels/thread, 128-thread CTAs (grid 2048, 8 CTAs/SM).
// Bilateral weights (raw fp32 + invsum) + iter 1. No per-tap arrays:
// pass 1 computes only maxn2; pass 2 recomputes d2 via |Pk|^2+|Pi|^2-2Pk.Pi.
// ---------------------------------------------------------------------------
__global__ __launch_bounds__(NTHR,8) void k_pre(const float* __restrict__ pts,
                                                const float* __restrict__ nrm,
                                                float* __restrict__ P1)
{
    __shared__ float4 sP [SH][SW];   // (Px,Py,Pz,|P|^2)
    __shared__ float4 sND[SH][SW];   // (Nx,Ny,Nz,D)  D = N.P
    const int b  = blockIdx.z;
    const int x0 = blockIdx.x*TX, y0 = blockIdx.y*TILEH;
    const float* pb = pts + b*3*HW;
    const float* nb = nrm + b*3*HW;

    for (int i = threadIdx.y*TX + threadIdx.x; i < SW*SH; i += NTHR) {
        int cy = i/SW, cx = i - cy*SW;
        int gx = x0+cx-2, gy = y0+cy-2;
        float px=0.f,py=0.f,pz=0.f,nx=0.f,ny=0.f,nz=0.f;
        if ((unsigned)gx < Wd && (unsigned)gy < Hd) {
            int o = gy*Wd + gx;
            px = pb[o]; py = pb[o+HW]; pz = pb[o+2*HW];
            nx = nb[o]; ny = nb[o+HW]; nz = nb[o+2*HW];
        }
        sP [cy][cx] = make_float4(px,py,pz, px*px + py*py + pz*pz);
        sND[cy][cx] = make_float4(nx,ny,nz, px*nx + py*ny + pz*nz);
    }
    __syncthreads();

    const int tx = threadIdx.x, ty = threadIdx.y;
    const int r0 = ty*VY;               // tile-local top row of this pair

    // centers (pixel A = row r0, pixel B = row r0+1)
    const float4 pcA = sP [r0+2][tx+2], pcB = sP [r0+3][tx+2];
    const float4 ncA = sND[r0+2][tx+2], ncB = sND[r0+3][tx+2];

    // Pass 1: max squared distance per pixel (shared row reads serve both)
    float maxA = 0.f, maxB = 0.f;
    #pragma unroll
    for (int j = 0; j < 6; j++) {
        #pragma unroll
        for (int dx = 0; dx < 5; dx++) {
            float4 p = sP[r0+j][tx+dx];
            if (j <= 4) {
                float d2 = (p.w + pcA.w) - 2.f*(p.x*pcA.x + p.y*pcA.y + p.z*pcA.z);
                maxA = fmaxf(maxA, d2);
            }
            if (j >= 1) {
                float d2 = (p.w + pcB.w) - 2.f*(p.x*pcB.x + p.y*pcB.y + p.z*pcB.z);
                maxB = fmaxf(maxB, d2);
            }
        }
    }
    float sigA = sqrtf(maxA)*0.2f + 1e-5f;
    float sigB = sqrtf(maxB)*0.2f + 1e-5f;
    float nsA = -0.5f/(sigA*sigA);
    float nsB = -0.5f/(sigB*sigB);

    // Pass 2: recompute d2, w = exp(ns*d2 - 4.5*(1-cos)^2); stage groups of 4
    // for 128-bit stores; accumulate wsum + unnormalized improvement.
    const int gx = x0+tx;
    const int gyA = y0+r0;
    const int idA = (b*Hd + gyA)*Wd + gx;
    const int idB = idA + Wd;
    float wsA=0.f, axA=0.f, ayA=0.f, azA=0.f, a0=0.f, a1=0.f, a2=0.f;
    float wsB=0.f, axB=0.f, ayB=0.f, azB=0.f, b0=0.f, b1=0.f, b2=0.f;
    #pragma unroll
    for (int j = 0; j < 6; j++) {
        #pragma unroll
        for (int dx = 0; dx < 5; dx++) {
            float4 p  = sP [r0+j][tx+dx];
            float4 nd = sND[r0+j][tx+dx];
            if (j <= 4) {
                int k = j*5 + dx;
                float d2   = (p.w + pcA.w) - 2.f*(p.x*pcA.x + p.y*pcA.y + p.z*pcA.z);
                float cosv = ncA.x*nd.x + ncA.y*nd.y + ncA.z*nd.z;
                float e = 1.f - cosv;
                float w = __expf(d2*nsA - 4.5f*e*e);
                wsA += w;
                float dot = nd.w - (nd.x*pcA.x + nd.y*pcA.y + nd.z*pcA.z);
                float t = w*dot;
                axA += t*nd.x; ayA += t*nd.y; azA += t*nd.z;
                int m = k & 3;
                if (k == 24)     g_w1[idA] = w;
                else if (m == 0) a0 = w;
                else if (m == 1) a1 = w;
                else if (m == 2) a2 = w;
                else             g_w4[(k>>2)*NP + idA] = make_float4(a0,a1,a2,w);
            }
            if (j >= 1) {
                int k = (j-1)*5 + dx;
                float d2   = (p.w + pcB.w) - 2.f*(p.x*pcB.x + p.y*pcB.y + p.z*pcB.z);
                float cosv = ncB.x*nd.x + ncB.y*nd.y + ncB.z*nd.z;
                float e = 1.f - cosv;
                float w = __expf(d2*nsB - 4.5f*e*e);
                wsB += w;
                float dot = nd.w - (nd.x*pcB.x + nd.y*pcB.y + nd.z*pcB.z);
                float t = w*dot;
                axB += t*nd.x; ayB += t*nd.y; azB += t*nd.z;
                int m = k & 3;
                if (k == 24)     g_w1[idB] = w;
                else if (m == 0) b0 = w;
                else if (m == 1) b1 = w;
                else if (m == 2) b2 = w;
                else             g_w4[(k>>2)*NP + idB] = make_float4(b0,b1,b2,w);
            }
        }
    }
    float isA = 1.f/wsA, isB = 1.f/wsB;
    g_is[idA] = isA;
    g_is[idB] = isB;

    const int oA = b*3*HW + gyA*Wd + gx;
    const int oB = oA + Wd;
    P1[oA]      = pcA.x + axA*isA;
    P1[oA+HW]   = pcA.y + ayA*isA;
    P1[oA+2*HW] = pcA.z + azA*isA;
    P1[oB]      = pcB.x + axB*isB;
    P1[oB+HW]   = pcB.y + ayB*isB;
    P1[oB+2*HW] = pcB.z + azB*isB;
}

// ---------------------------------------------------------------------------
// k_iter: V=2 pixels/thread, 128-thread CTAs.
// P_out = P_cur + invsum*sum_k w_k(D_k-N_k.P_i)N_k; weights streamed one
// float4 per 4 taps per pixel (low liveness).
// ---------------------------------------------------------------------------
template<bool LAST>
__global__ __launch_bounds__(NTHR,8) void k_iter(const float* __restrict__ Pcur,
                                                 const float* __restrict__ nrm,
                                                 const float* __restrict__ ptsOrig,
                                                 float* __restrict__ Pout)
{
    __shared__ float4 sND[SH][SW];   // (Nx,Ny,Nz,D) with D = N.Pcur
    const int b  = blockIdx.z;
    const int x0 = blockIdx.x*TX, y0 = blockIdx.y*TILEH;
    const float* pb = Pcur + b*3*HW;
    const float* nb = nrm  + b*3*HW;

    for (int i = threadIdx.y*TX + threadIdx.x; i < SW*SH; i += NTHR) {
        int cy = i/SW, cx = i - cy*SW;
        int gx = x0+cx-2, gy = y0+cy-2;
        float px=0.f,py=0.f,pz=0.f,nx=0.f,ny=0.f,nz=0.f;
        if ((unsigned)gx < Wd && (unsigned)gy < Hd) {
            int o = gy*Wd + gx;
            px = pb[o]; py = pb[o+HW]; pz = pb[o+2*HW];
            nx = nb[o]; ny = nb[o+HW]; nz = nb[o+2*HW];
        }
        sND[cy][cx] = make_float4(nx,ny,nz, px*nx + py*ny + pz*nz);
    }
    __syncthreads();

    const int tx = threadIdx.x, ty = threadIdx.y;
    const int r0 = ty*VY;
    const int gx = x0+tx;
    const int gyA = y0+r0;
    const int idA = (b*Hd + gyA)*Wd + gx;
    const int idB = idA + Wd;
    const int oA  = b*3*HW + gyA*Wd + gx;
    const int oB  = oA + Wd;

    const float pAx = Pcur[oA],    pAy = Pcur[oA+HW],    pAz = Pcur[oA+2*HW];
    const float pBx = Pcur[oB],    pBy = Pcur[oB+HW],    pBz = Pcur[oB+2*HW];
    const float isA = g_is[idA],   isB = g_is[idB];

    float axA=0.f, ayA=0.f, azA=0.f;
    float axB=0.f, ayB=0.f, azB=0.f;
    float4 qA = make_float4(0,0,0,0), qB = make_float4(0,0,0,0);
    #pragma unroll
    for (int j = 0; j < 6; j++) {
        #pragma unroll
        for (int dx = 0; dx < 5; dx++) {
            float4 nd = sND[r0+j][tx+dx];
            if (j <= 4) {
                int k = j*5 + dx;
                float w;
                if (k == 24) w = g_w1[idA];
                else {
                    int m = k & 3;
                    if (m == 0) qA = g_w4[(k>>2)*NP + idA];
                    w = (m==0)?qA.x:(m==1)?qA.y:(m==2)?qA.z:qA.w;
                }
                float dot = nd.w - (nd.x*pAx + nd.y*pAy + nd.z*pAz);
                float t = w*dot;
                axA += t*nd.x; ayA += t*nd.y; azA += t*nd.z;
            }
            if (j >= 1) {
                int k = (j-1)*5 + dx;
                float w;
                if (k == 24) w = g_w1[idB];
                else {
                    int m = k & 3;
                    if (m == 0) qB = g_w4[(k>>2)*NP + idB];
                    w = (m==0)?qB.x:(m==1)?qB.y:(m==2)?qB.z:qB.w;
                }
                float dot = nd.w - (nd.x*pBx + nd.y*pBy + nd.z*pBz);
                float t = w*dot;
                axB += t*nd.x; ayB += t*nd.y; azB += t*nd.z;
            }
        }
    }

    float oxA = pAx + axA*isA, oyA = pAy + ayA*isA, ozA = pAz + azA*isA;
    float oxB = pBx + axB*isB, oyB = pBy + ayB*isB, ozB = pBz + azB*isB;
    if (LAST) {
        oxA = (ptsOrig[oA]      != 0.f) ? oxA : 0.f;
        oyA = (ptsOrig[oA+HW]   != 0.f) ? oyA : 0.f;
        ozA = (ptsOrig[oA+2*HW] != 0.f) ? ozA : 0.f;
        oxB = (ptsOrig[oB]      != 0.f) ? oxB : 0.f;
        oyB = (ptsOrig[oB+HW]   != 0.f) ? oyB : 0.f;
        ozB = (ptsOrig[oB+2*HW] != 0.f) ? ozB : 0.f;
    }
    Pout[oA] = oxA; Pout[oA+HW] = oyA; Pout[oA+2*HW] = ozA;
    Pout[oB] = oxB; Pout[oB+HW] = oyB; Pout[oB+2*HW] = ozB;
}

extern "C" void kernel_launch(void* const* d_in, const int* in_sizes, int n_in,
                              void* d_out, int out_size)
{
    const float* pts = (const float*)d_in[0];
    const float* nrm = (const float*)d_in[1];
    float* out = (float*)d_out;

    float *PA, *PB;
    cudaGetSymbolAddress((void**)&PA, g_PA);
    cudaGetSymbolAddress((void**)&PB, g_PB);

    dim3 block(TX, TY);
    dim3 grid(Wd/TX, Hd/TILEH, Bd);   // 16 x 32 x 4 = 2048 CTAs

    k_pre<<<grid, block>>>(pts, nrm, PA);                 // weights + iter 1
    k_iter<false><<<grid, block>>>(PA, nrm, pts, PB);     // iter 2
    k_iter<true ><<<grid, block>>>(PB, nrm, pts, out);    // iter 3 + mask
}